// round 6
// baseline (speedup 1.0000x reference)
#include <cuda_runtime.h>
#include <cstdint>

#define B_    32
#define T_    4096
#define D_    256
#define H_    256
#define G4_   1024
#define HOR_  24

typedef unsigned long long ull;

// ---------------- device scratch (static; no runtime allocation) ----------------
__device__ __align__(16) float g_XG[(size_t)B_ * T_ * G4_];   // [m=b*T+t][n] fp32, 512 MB
__device__ __align__(16) float g_h[B_ * H_];                  // final hidden state [b][j]

// ---------------- helpers ----------------
__device__ __forceinline__ ull pack2(float x, float y) {
    ull r;
    asm("mov.b64 %0, {%1, %2};" : "=l"(r) : "f"(x), "f"(y));
    return r;
}
__device__ __forceinline__ void unpack2(ull v, float& x, float& y) {
    asm("mov.b64 {%0, %1}, %2;" : "=f"(x), "=f"(y) : "l"(v));
}
__device__ __forceinline__ ull fma2(ull a, ull w, ull x) {
    asm("fma.rn.f32x2 %0, %1, %2, %0;" : "+l"(a) : "l"(w), "l"(x));
    return a;
}
__device__ __forceinline__ float ex2f(float x) {
    float y; asm("ex2.approx.f32 %0, %1;" : "=f"(y) : "f"(x)); return y;
}
__device__ __forceinline__ float rcpf(float x) {
    float y; asm("rcp.approx.f32 %0, %1;" : "=f"(y) : "f"(x)); return y;
}
__device__ __forceinline__ float sigf(float x) {
    return rcpf(1.f + ex2f(-1.4426950408889634f * x));
}
__device__ __forceinline__ float tanh_f(float x) {
    return fmaf(2.f, rcpf(1.f + ex2f(-2.8853900817779268f * x)), -1.f);
}
__device__ __forceinline__ unsigned smem_u32(const void* p) {
    return (unsigned)__cvta_generic_to_shared(p);
}
__device__ __forceinline__ void mbar_wait_cluster(unsigned mb, unsigned par) {
    asm volatile(
        "{\n\t"
        ".reg .pred P;\n\t"
        "WL_%=:\n\t"
        "mbarrier.try_wait.parity.acquire.cluster.shared::cta.b64 P, [%0], %1, 0x989680;\n\t"
        "@!P bra WL_%=;\n\t"
        "}"
        :: "r"(mb), "r"(par) : "memory");
}

// ---------------- kernel 1: SGEMM  XG[m][n] = A[m][k] @ W[k][n] + bl[n] ----------------
#define MT 128
#define NT 64
#define KT 16

__global__ void __launch_bounds__(256) k_xgemm(const float* __restrict__ A,
                                               const float* __restrict__ W,
                                               const float* __restrict__ bl) {
    __shared__ __align__(16) float As[2][KT][MT];
    __shared__ __align__(16) float Bs[2][KT][NT];
    const int tid = threadIdx.x;
    const int m0 = blockIdx.x * MT;
    const int n0 = blockIdx.y * NT;

    const int ar0 = tid >> 2;
    const int akc = (tid & 3) * 4;
    const int bk = tid >> 4;
    const int bn = (tid & 15) * 4;
    const int mt = tid >> 4;
    const int nt = tid & 15;

    const float* Ar0 = A + (size_t)(m0 + ar0) * D_ + akc;
    const float* Ar1 = A + (size_t)(m0 + 64 + ar0) * D_ + akc;
    const float* Wp  = W + (size_t)bk * G4_ + n0 + bn;

    float4 a0 = *(const float4*)(Ar0);
    float4 a1 = *(const float4*)(Ar1);
    float4 b0 = *(const float4*)(Wp);
    #pragma unroll
    for (int i = 0; i < 4; i++) {
        As[0][akc + i][ar0]      = ((const float*)&a0)[i];
        As[0][akc + i][64 + ar0] = ((const float*)&a1)[i];
    }
    *(float4*)&Bs[0][bk][bn] = b0;
    __syncthreads();

    ull acc[4][4];
    #pragma unroll
    for (int p = 0; p < 4; p++)
        #pragma unroll
        for (int n = 0; n < 4; n++) acc[p][n] = 0ull;

    #pragma unroll 1
    for (int kt = 0; kt < D_ / KT; kt++) {
        const int cur = kt & 1, nxt = cur ^ 1;
        if (kt + 1 < D_ / KT) {
            a0 = *(const float4*)(Ar0 + (kt + 1) * KT);
            a1 = *(const float4*)(Ar1 + (kt + 1) * KT);
            b0 = *(const float4*)(Wp + (size_t)(kt + 1) * KT * G4_);
        }
        #pragma unroll
        for (int k = 0; k < KT; k++) {
            const ull* ap = (const ull*)&As[cur][k][mt * 8];
            const float* bp = &Bs[cur][k][nt * 4];
            ull am0 = ap[0], am1 = ap[1], am2 = ap[2], am3 = ap[3];
            #pragma unroll
            for (int n = 0; n < 4; n++) {
                ull bb = pack2(bp[n], bp[n]);
                acc[0][n] = fma2(acc[0][n], am0, bb);
                acc[1][n] = fma2(acc[1][n], am1, bb);
                acc[2][n] = fma2(acc[2][n], am2, bb);
                acc[3][n] = fma2(acc[3][n], am3, bb);
            }
        }
        if (kt + 1 < D_ / KT) {
            #pragma unroll
            for (int i = 0; i < 4; i++) {
                As[nxt][akc + i][ar0]      = ((const float*)&a0)[i];
                As[nxt][akc + i][64 + ar0] = ((const float*)&a1)[i];
            }
            *(float4*)&Bs[nxt][bk][bn] = b0;
            __syncthreads();
        }
    }

    float bias[4];
    #pragma unroll
    for (int n = 0; n < 4; n++) bias[n] = bl[n0 + nt * 4 + n];
    float* Cr = g_XG + (size_t)(m0 + mt * 8) * G4_ + n0 + nt * 4;
    #pragma unroll
    for (int p = 0; p < 4; p++) {
        float e[4], o[4];
        #pragma unroll
        for (int n = 0; n < 4; n++) {
            unpack2(acc[p][n], e[n], o[n]);
            e[n] += bias[n]; o[n] += bias[n];
        }
        *(float4*)(Cr + (size_t)(2 * p) * G4_)     = make_float4(e[0], e[1], e[2], e[3]);
        *(float4*)(Cr + (size_t)(2 * p + 1) * G4_) = make_float4(o[0], o[1], o[2], o[3]);
    }
}

// ---------------- kernel 2: clustered LSTM recurrence ----------------
// 16 clusters x 8 CTAs, occ 1 (regs force it). Cluster g owns batches {2g, 2g+1}.
// CTA rank r owns j in [32r, 32r+32). Thread (w = tid>>5, l = tid&31): K-chunk
// [32w, 32w+32), hidden j = 32r + l, 4 gates x 2 batches. ALL weights in registers
// (64 f32x2 pairs = 128 regs) -> zero weight LDS; h loads are SMEM broadcasts.
struct RnnSmem {
    float red[8][4][2][32];    // [w][q][b][l] K-chunk partials, 8 KB
    float gs[4][2][32];        // [q][b][l] gate sums, 1 KB
    float hs[2][2][H_];        // [parity][b][j] hidden state, 4 KB
    float xg_s[4][2][32];      // [q][b][l] staged XG, 1 KB
    ull   mbar[2];
};

__global__ void __launch_bounds__(256, 1) __cluster_dims__(8, 1, 1)
k_rnn(const float* __restrict__ W) {
    __shared__ RnnSmem S;

    const int tid = threadIdx.x;
    const int w   = tid >> 5;
    const int l   = tid & 31;
    const int r   = blockIdx.x & 7;
    const int g   = blockIdx.x >> 3;
    const int kbase = w * 32;
    const int j   = r * 32 + l;

    // all weights register-stationary: 4 gates x 16 K-pairs
    ull wreg[64];
    #pragma unroll
    for (int q = 0; q < 4; q++) {
        int n = q * 256 + j;
        #pragma unroll
        for (int p = 0; p < 16; p++) {
            int k = kbase + 2 * p;
            wreg[q * 16 + p] = pack2(W[(size_t)(D_ + k) * G4_ + n],
                                     W[(size_t)(D_ + k + 1) * G4_ + n]);
        }
    }
    for (int i = tid; i < 2 * H_; i += 256) ((float*)S.hs[0])[i] = 0.f;
    float c_state = 0.f;   // valid in warps 0,1

    const unsigned sbase  = smem_u32(&S);
    const unsigned hs_off = (unsigned)((char*)&S.hs[0][0][0] - (char*)&S);
    const unsigned mb_off = (unsigned)((char*)&S.mbar[0] - (char*)&S);

    if (tid == 0) {
        asm volatile("mbarrier.init.shared.b64 [%0], 2;" :: "r"(sbase + mb_off)     : "memory");
        asm volatile("mbarrier.init.shared.b64 [%0], 2;" :: "r"(sbase + mb_off + 8) : "memory");
    }
    __syncthreads();
    asm volatile("barrier.cluster.arrive.aligned;" ::: "memory");
    asm volatile("barrier.cluster.wait.aligned;"   ::: "memory");

    // remote smem bases (only epilogue warps need them)
    unsigned rbase[8];
    if (w < 2) {
        #pragma unroll
        for (int d = 0; d < 8; d++)
            asm("mapa.shared::cluster.u32 %0, %1, %2;" : "=r"(rbase[d]) : "r"(sbase), "r"(d));
    }

    // XG stream: warp w -> (gate qx = w>>1, batch bx = w&1); 128B line per warp per step
    const int qx = w >> 1, bx = w & 1;
    const float* xgp = g_XG + ((size_t)(2 * g + bx) * T_) * G4_ + qx * 256 + j;
    float xv = __ldcs(xgp);

    #pragma unroll 1
    for (int t = 0; t < T_; ++t) {
        if (t > 0)
            mbar_wait_cluster(sbase + mb_off + ((t - 1) & 1) * 8, ((t - 1) >> 1) & 1);

        S.xg_s[qx][bx][l] = xv;
        if (t + 1 < T_) xv = __ldcs(xgp + (size_t)(t + 1) * G4_);

        const ull* hp0 = (const ull*)&S.hs[t & 1][0][kbase];
        const ull* hp1 = (const ull*)&S.hs[t & 1][1][kbase];
        ull acc[8];
        #pragma unroll
        for (int i = 0; i < 8; i++) acc[i] = 0ull;

        #pragma unroll
        for (int p = 0; p < 16; p++) {
            ull h0 = hp0[p];
            ull h1 = hp1[p];
            #pragma unroll
            for (int q = 0; q < 4; q++) {
                acc[q]     = fma2(acc[q],     wreg[q * 16 + p], h0);
                acc[4 + q] = fma2(acc[4 + q], wreg[q * 16 + p], h1);
            }
        }
        #pragma unroll
        for (int q = 0; q < 4; q++) {
            float ax, ay;
            unpack2(acc[q], ax, ay);
            S.red[w][q][0][l] = ax + ay;
            unpack2(acc[4 + q], ax, ay);
            S.red[w][q][1][l] = ax + ay;
        }
        __syncthreads();

        // reduce: thread -> (q2, b2, l)
        {
            const int q2 = tid >> 6;
            const int b2 = (tid >> 5) & 1;
            float s = S.xg_s[q2][b2][l];
            #pragma unroll
            for (int kh = 0; kh < 8; kh++) s += S.red[kh][q2][b2][l];
            S.gs[q2][b2][l] = s;
        }
        __syncthreads();

        // activations + state update + DSMEM broadcast: warps 0 (b=0) and 1 (b=1)
        if (w < 2) {
            const int b3 = w;
            float gi = S.gs[0][b3][l];
            float gG = S.gs[1][b3][l];
            float gf = S.gs[2][b3][l];
            float go = S.gs[3][b3][l];
            c_state = sigf(gf + 1.f) * c_state + sigf(gi) * tanh_f(gG);
            float h = sigf(go) * tanh_f(c_state);
            unsigned hbits = __float_as_uint(h);

            const unsigned dst_off = hs_off + (unsigned)(((((t + 1) & 1) * 2 + b3) * H_ + j) * 4);
            const unsigned mbr_off = mb_off + (unsigned)((t & 1) * 8);
            #pragma unroll
            for (int d = 0; d < 8; d++) {
                asm volatile(
                    "st.async.weak.shared::cluster.mbarrier::complete_tx::bytes.u32 [%0], %1, [%2];"
                    :: "r"(rbase[d] + dst_off), "r"(hbits), "r"(rbase[d] + mbr_off)
                    : "memory");
            }
            if (l == 0) {
                asm volatile("mbarrier.arrive.expect_tx.shared.b64 _, [%0], 1024;"
                             :: "r"(sbase + mbr_off) : "memory");
            }
            if (t == T_ - 1) g_h[(2 * g + b3) * H_ + j] = h;
        }
    }
    // drain final phase so no CTA exits with peer traffic in flight
    mbar_wait_cluster(sbase + mb_off + ((T_ - 1) & 1) * 8, ((T_ - 1) >> 1) & 1);
}

// ---------------- kernel 3: out = (h @ Wfc + bfc) @ Wout + bout ----------------
__global__ void __launch_bounds__(256) k_fc(const float* __restrict__ Wfc,
                                            const float* __restrict__ bfc,
                                            const float* __restrict__ Wout,
                                            const float* __restrict__ bout,
                                            float* __restrict__ out) {
    __shared__ float tmp[H_];
    int b = blockIdx.x;
    int jj = threadIdx.x;
    const float* h = &g_h[b * H_];
    float s = bfc[jj];
    #pragma unroll 8
    for (int k = 0; k < H_; k++) s += h[k] * Wfc[(size_t)k * H_ + jj];
    tmp[jj] = s;
    __syncthreads();
    if (jj < HOR_) {
        float o = bout[jj];
        #pragma unroll 8
        for (int k = 0; k < H_; k++) o += tmp[k] * Wout[(size_t)k * HOR_ + jj];
        out[b * HOR_ + jj] = o;
    }
}

// ---------------- launch ----------------
extern "C" void kernel_launch(void* const* d_in, const int* in_sizes, int n_in,
                              void* d_out, int out_size) {
    const float* x      = (const float*)d_in[0];
    const float* W_lstm = (const float*)d_in[1];
    const float* b_lstm = (const float*)d_in[2];
    const float* W_fc   = (const float*)d_in[3];
    const float* b_fc   = (const float*)d_in[4];
    const float* W_out  = (const float*)d_in[5];
    const float* b_out  = (const float*)d_in[6];
    float* out = (float*)d_out;

    k_xgemm<<<dim3((B_ * T_) / MT, G4_ / NT), 256>>>(x, W_lstm, b_lstm);
    k_rnn<<<128, 256>>>(W_lstm);
    k_fc<<<B_, 256>>>(W_fc, b_fc, W_out, b_out, out);
}

// round 7
// speedup vs baseline: 1.1498x; 1.1498x over previous
#include <cuda_runtime.h>
#include <cstdint>

#define B_    32
#define T_    4096
#define D_    256
#define H_    256
#define G4_   1024
#define HOR_  24

#define RNN_CTAS 128            // 16 clusters x 8 CTAs, 2 batches per cluster
#define NTILES   16384          // 32 tchunk x 32 b x 16 ntile

typedef unsigned long long ull;

// ---------------- device scratch (static; no runtime allocation) ----------------
__device__ __align__(16) float g_XG[(size_t)B_ * T_ * G4_];   // [m=b*T+t][n] fp32, 512 MB
__device__ __align__(16) float g_h[B_ * H_];                  // final hidden state [b][j]
__device__ unsigned g_flag[B_ * 32];                          // [b][tchunk] -> counts to 16

// ---------------- helpers ----------------
__device__ __forceinline__ ull pack2(float x, float y) {
    ull r;
    asm("mov.b64 %0, {%1, %2};" : "=l"(r) : "f"(x), "f"(y));
    return r;
}
__device__ __forceinline__ void unpack2(ull v, float& x, float& y) {
    asm("mov.b64 {%0, %1}, %2;" : "=f"(x), "=f"(y) : "l"(v));
}
__device__ __forceinline__ ull fma2(ull a, ull w, ull x) {
    asm("fma.rn.f32x2 %0, %1, %2, %0;" : "+l"(a) : "l"(w), "l"(x));
    return a;
}
__device__ __forceinline__ float ex2f(float x) {
    float y; asm("ex2.approx.f32 %0, %1;" : "=f"(y) : "f"(x)); return y;
}
__device__ __forceinline__ float rcpf(float x) {
    float y; asm("rcp.approx.f32 %0, %1;" : "=f"(y) : "f"(x)); return y;
}
__device__ __forceinline__ float sigf(float x) {
    return rcpf(1.f + ex2f(-1.4426950408889634f * x));
}
__device__ __forceinline__ float tanh_f(float x) {
    return fmaf(2.f, rcpf(1.f + ex2f(-2.8853900817779268f * x)), -1.f);
}
__device__ __forceinline__ unsigned smem_u32(const void* p) {
    return (unsigned)__cvta_generic_to_shared(p);
}
__device__ __forceinline__ void mbar_wait_cluster(unsigned mb, unsigned par) {
    asm volatile(
        "{\n\t"
        ".reg .pred P;\n\t"
        "WL_%=:\n\t"
        "mbarrier.try_wait.parity.acquire.cluster.shared::cta.b64 P, [%0], %1, 0x989680;\n\t"
        "@!P bra WL_%=;\n\t"
        "}"
        :: "r"(mb), "r"(par) : "memory");
}
__device__ __forceinline__ void wait_flag16(const unsigned* f) {
    unsigned v;
    do {
        asm volatile("ld.acquire.gpu.u32 %0, [%1];" : "=r"(v) : "l"(f) : "memory");
    } while (v != 16u);
}

// ---------------- kernel 0: reset flags ----------------
__global__ void k_init() {
    int i = blockIdx.x * 256 + threadIdx.x;
    if (i < B_ * 32) g_flag[i] = 0u;
}

// ================= fused kernel: role split =================
#define MT 128
#define NT 64
#define KT 16

struct GemmSmem {
    float As[2][KT][MT];   // 16 KB
    float Bs[2][KT][NT];   // 8 KB
};

struct RnnSmem {
    ull   Wst[8][6][4][32];    // [w][p][q][l] streamed weight pairs, 48 KB
    float red[8][4][2][32];    // [w][q][b][l] K-chunk partials, 8 KB
    float gs[4][2][32];        // [q][b][l] gate sums, 1 KB
    float hs[2][2][H_];        // [parity][b][j] hidden, 4 KB
    float xg_s[4][2][32];      // [q][b][l] staged XG, 1 KB
    ull   mbar[2];
};

// ---- gemm role: one 128x64 tile of XG = A @ W + bl, then release its flag ----
__device__ __forceinline__ void gemm_role(unsigned char* smem_raw,
                                          const float* __restrict__ A,
                                          const float* __restrict__ W,
                                          const float* __restrict__ bl,
                                          int tau) {
    GemmSmem* G = (GemmSmem*)smem_raw;
    const int tid = threadIdx.x;
    const int tc     = tau >> 9;          // t-chunk 0..31 (t-major ordering)
    const int rem    = tau & 511;
    const int bb     = rem >> 4;          // batch 0..31
    const int ntile  = rem & 15;
    const int m0 = bb * T_ + tc * MT;
    const int n0 = ntile * NT;

    const int ar0 = tid >> 2;
    const int akc = (tid & 3) * 4;
    const int bk = tid >> 4;
    const int bn = (tid & 15) * 4;
    const int mt = tid >> 4;
    const int nt = tid & 15;

    const float* Ar0 = A + (size_t)(m0 + ar0) * D_ + akc;
    const float* Ar1 = A + (size_t)(m0 + 64 + ar0) * D_ + akc;
    const float* Wp  = W + (size_t)bk * G4_ + n0 + bn;

    float4 a0 = *(const float4*)(Ar0);
    float4 a1 = *(const float4*)(Ar1);
    float4 b0 = *(const float4*)(Wp);
    #pragma unroll
    for (int i = 0; i < 4; i++) {
        G->As[0][akc + i][ar0]      = ((const float*)&a0)[i];
        G->As[0][akc + i][64 + ar0] = ((const float*)&a1)[i];
    }
    *(float4*)&G->Bs[0][bk][bn] = b0;
    __syncthreads();

    ull acc[4][4];
    #pragma unroll
    for (int p = 0; p < 4; p++)
        #pragma unroll
        for (int n = 0; n < 4; n++) acc[p][n] = 0ull;

    #pragma unroll 1
    for (int kt = 0; kt < D_ / KT; kt++) {
        const int cur = kt & 1, nxt = cur ^ 1;
        if (kt + 1 < D_ / KT) {
            a0 = *(const float4*)(Ar0 + (kt + 1) * KT);
            a1 = *(const float4*)(Ar1 + (kt + 1) * KT);
            b0 = *(const float4*)(Wp + (size_t)(kt + 1) * KT * G4_);
        }
        #pragma unroll
        for (int k = 0; k < KT; k++) {
            const ull* ap = (const ull*)&G->As[cur][k][mt * 8];
            const float* bp = &G->Bs[cur][k][nt * 4];
            ull am0 = ap[0], am1 = ap[1], am2 = ap[2], am3 = ap[3];
            #pragma unroll
            for (int n = 0; n < 4; n++) {
                ull bbv = pack2(bp[n], bp[n]);
                acc[0][n] = fma2(acc[0][n], am0, bbv);
                acc[1][n] = fma2(acc[1][n], am1, bbv);
                acc[2][n] = fma2(acc[2][n], am2, bbv);
                acc[3][n] = fma2(acc[3][n], am3, bbv);
            }
        }
        if (kt + 1 < D_ / KT) {
            #pragma unroll
            for (int i = 0; i < 4; i++) {
                G->As[nxt][akc + i][ar0]      = ((const float*)&a0)[i];
                G->As[nxt][akc + i][64 + ar0] = ((const float*)&a1)[i];
            }
            *(float4*)&G->Bs[nxt][bk][bn] = b0;
            __syncthreads();
        }
    }

    float bias[4];
    #pragma unroll
    for (int n = 0; n < 4; n++) bias[n] = bl[n0 + nt * 4 + n];
    float* Cr = g_XG + (size_t)(m0 + mt * 8) * G4_ + n0 + nt * 4;
    #pragma unroll
    for (int p = 0; p < 4; p++) {
        float e[4], o[4];
        #pragma unroll
        for (int n = 0; n < 4; n++) {
            unpack2(acc[p][n], e[n], o[n]);
            e[n] += bias[n]; o[n] += bias[n];
        }
        *(float4*)(Cr + (size_t)(2 * p) * G4_)     = make_float4(e[0], e[1], e[2], e[3]);
        *(float4*)(Cr + (size_t)(2 * p + 1) * G4_) = make_float4(o[0], o[1], o[2], o[3]);
    }

    // publish: all tile stores done -> release one count on the (b, tchunk) flag
    __syncthreads();
    if (tid == 0) {
        asm volatile("red.release.gpu.global.add.u32 [%0], 1;"
                     :: "l"(&g_flag[bb * 32 + tc]) : "memory");
    }
}

// ---- rnn role: cluster g owns batches {2g, 2g+1}; rank r owns j in [32r, 32r+32) ----
__device__ __forceinline__ void rnn_role(unsigned char* smem_raw,
                                         const float* __restrict__ W) {
    RnnSmem* S = (RnnSmem*)smem_raw;

    const int tid = threadIdx.x;
    const int w   = tid >> 5;
    const int l   = tid & 31;
    const int r   = blockIdx.x & 7;
    const int g   = blockIdx.x >> 3;
    const int kbase = w * 32;
    const int j   = r * 32 + l;

    // weights: 40 reg pairs (10 per gate) + 24 streamed pairs (6 per gate)
    ull wreg[40];
    #pragma unroll
    for (int q = 0; q < 4; q++) {
        int n = q * 256 + j;
        #pragma unroll
        for (int p = 0; p < 10; p++) {
            int k = kbase + 2 * p;
            wreg[q * 10 + p] = pack2(W[(size_t)(D_ + k) * G4_ + n],
                                     W[(size_t)(D_ + k + 1) * G4_ + n]);
        }
        #pragma unroll
        for (int p = 0; p < 6; p++) {
            int k = kbase + 20 + 2 * p;
            S->Wst[w][p][q][l] = pack2(W[(size_t)(D_ + k) * G4_ + n],
                                       W[(size_t)(D_ + k + 1) * G4_ + n]);
        }
    }
    for (int i = tid; i < 2 * H_; i += 256) ((float*)S->hs[0])[i] = 0.f;
    float c_state = 0.f;   // valid in warps 0,1

    const unsigned sbase  = smem_u32(S);
    const unsigned hs_off = (unsigned)((char*)&S->hs[0][0][0] - (char*)S);
    const unsigned mb_off = (unsigned)((char*)&S->mbar[0] - (char*)S);

    if (tid == 0) {
        asm volatile("mbarrier.init.shared.b64 [%0], 2;" :: "r"(sbase + mb_off)     : "memory");
        asm volatile("mbarrier.init.shared.b64 [%0], 2;" :: "r"(sbase + mb_off + 8) : "memory");
    }
    __syncthreads();
    asm volatile("barrier.cluster.arrive.aligned;" ::: "memory");
    asm volatile("barrier.cluster.wait.aligned;"   ::: "memory");

    // XG stream: warp w -> (gate qx = w>>1, batch bx = w&1)
    const int qx = w >> 1, bx = w & 1;
    const float* xgp = g_XG + ((size_t)(2 * g + bx) * T_) * G4_ + qx * 256 + j;
    float xv = 0.f;

    #pragma unroll 1
    for (int t = 0; t < T_; ++t) {
        // chunk boundary: wait until x-GEMM published this 128-step slab for both batches
        if ((t & 127) == 0) {
            if (tid == 0) {
                wait_flag16(&g_flag[(2 * g) * 32 + (t >> 7)]);
                wait_flag16(&g_flag[(2 * g + 1) * 32 + (t >> 7)]);
            }
            __syncthreads();
            xv = __ldcg(xgp + (size_t)t * G4_);
        }

        if (t > 0)
            mbar_wait_cluster(sbase + mb_off + ((t - 1) & 1) * 8, ((t - 1) >> 1) & 1);

        S->xg_s[qx][bx][l] = xv;
        if (((t + 1) & 127) != 0) xv = __ldcg(xgp + (size_t)(t + 1) * G4_);

        const ull* hp0 = (const ull*)&S->hs[t & 1][0][kbase];
        const ull* hp1 = (const ull*)&S->hs[t & 1][1][kbase];
        ull acc[8];
        #pragma unroll
        for (int i = 0; i < 8; i++) acc[i] = 0ull;

        #pragma unroll
        for (int p = 0; p < 10; p++) {
            ull h0 = hp0[p];
            ull h1 = hp1[p];
            #pragma unroll
            for (int q = 0; q < 4; q++) {
                acc[q]     = fma2(acc[q],     wreg[q * 10 + p], h0);
                acc[4 + q] = fma2(acc[4 + q], wreg[q * 10 + p], h1);
            }
        }
        const ull* wst = &S->Wst[w][0][0][l];
        #pragma unroll
        for (int p = 0; p < 6; p++) {
            ull h0 = hp0[10 + p];
            ull h1 = hp1[10 + p];
            #pragma unroll
            for (int q = 0; q < 4; q++) {
                ull wv = wst[p * 128 + q * 32];
                acc[q]     = fma2(acc[q],     wv, h0);
                acc[4 + q] = fma2(acc[4 + q], wv, h1);
            }
        }

        #pragma unroll
        for (int q = 0; q < 4; q++) {
            float ax, ay;
            unpack2(acc[q], ax, ay);
            S->red[w][q][0][l] = ax + ay;
            unpack2(acc[4 + q], ax, ay);
            S->red[w][q][1][l] = ax + ay;
        }
        __syncthreads();

        // reduce: thread -> (q2, b2, l)
        {
            const int q2 = tid >> 6;
            const int b2 = (tid >> 5) & 1;
            float s = S->xg_s[q2][b2][l];
            #pragma unroll
            for (int kh = 0; kh < 8; kh++) s += S->red[kh][q2][b2][l];
            S->gs[q2][b2][l] = s;
        }
        __syncthreads();

        // activations + DSMEM broadcast: warp 0 -> batch 0, warp 1 -> batch 1
        if (w < 2) {
            const int b3 = w;
            float gi = S->gs[0][b3][l];
            float gG = S->gs[1][b3][l];
            float gf = S->gs[2][b3][l];
            float go = S->gs[3][b3][l];
            c_state = sigf(gf + 1.f) * c_state + sigf(gi) * tanh_f(gG);
            float h = sigf(go) * tanh_f(c_state);
            unsigned hbits = __float_as_uint(h);

            const unsigned dst_off = hs_off + (unsigned)(((((t + 1) & 1) * 2 + b3) * H_ + j) * 4);
            const unsigned mbr_off = mb_off + (unsigned)((t & 1) * 8);
            #pragma unroll
            for (int d = 0; d < 8; d++) {
                unsigned rb;
                asm("mapa.shared::cluster.u32 %0, %1, %2;" : "=r"(rb) : "r"(sbase), "r"(d));
                asm volatile(
                    "st.async.weak.shared::cluster.mbarrier::complete_tx::bytes.u32 [%0], %1, [%2];"
                    :: "r"(rb + dst_off), "r"(hbits), "r"(rb + mbr_off)
                    : "memory");
            }
            if (l == 0) {
                asm volatile("mbarrier.arrive.expect_tx.shared.b64 _, [%0], 1024;"
                             :: "r"(sbase + mbr_off) : "memory");
            }
            if (t == T_ - 1) g_h[(2 * g + b3) * H_ + j] = h;
        }
    }
    // drain final phase so no CTA exits with peer traffic in flight
    mbar_wait_cluster(sbase + mb_off + ((T_ - 1) & 1) * 8, ((T_ - 1) >> 1) & 1);
}

__global__ void __launch_bounds__(256, 2) __cluster_dims__(8, 1, 1)
k_fused(const float* __restrict__ x, const float* __restrict__ W,
        const float* __restrict__ bl) {
    extern __shared__ __align__(16) unsigned char smem_raw[];
    if (blockIdx.x < RNN_CTAS) rnn_role(smem_raw, W);
    else                       gemm_role(smem_raw, x, W, bl, (int)blockIdx.x - RNN_CTAS);
}

// ---------------- kernel 3: out = (h @ Wfc + bfc) @ Wout + bout ----------------
__global__ void __launch_bounds__(256) k_fc(const float* __restrict__ Wfc,
                                            const float* __restrict__ bfc,
                                            const float* __restrict__ Wout,
                                            const float* __restrict__ bout,
                                            float* __restrict__ out) {
    __shared__ float tmp[H_];
    int b = blockIdx.x;
    int jj = threadIdx.x;
    const float* h = &g_h[b * H_];
    float s = bfc[jj];
    #pragma unroll 8
    for (int k = 0; k < H_; k++) s += h[k] * Wfc[(size_t)k * H_ + jj];
    tmp[jj] = s;
    __syncthreads();
    if (jj < HOR_) {
        float o = bout[jj];
        #pragma unroll 8
        for (int k = 0; k < H_; k++) o += tmp[k] * Wout[(size_t)k * HOR_ + jj];
        out[b * HOR_ + jj] = o;
    }
}

// ---------------- launch ----------------
extern "C" void kernel_launch(void* const* d_in, const int* in_sizes, int n_in,
                              void* d_out, int out_size) {
    const float* x      = (const float*)d_in[0];
    const float* W_lstm = (const float*)d_in[1];
    const float* b_lstm = (const float*)d_in[2];
    const float* W_fc   = (const float*)d_in[3];
    const float* b_fc   = (const float*)d_in[4];
    const float* W_out  = (const float*)d_in[5];
    const float* b_out  = (const float*)d_in[6];
    float* out = (float*)d_out;

    cudaFuncSetAttribute(k_fused, cudaFuncAttributeMaxDynamicSharedMemorySize,
                         (int)sizeof(RnnSmem));

    k_init<<<4, 256>>>();
    k_fused<<<RNN_CTAS + NTILES, 256, sizeof(RnnSmem)>>>(x, W_lstm, b_lstm);
    k_fc<<<B_, 256>>>(W_fc, b_fc, W_out, b_out, out);
}